// round 9
// baseline (speedup 1.0000x reference)
#include <cuda_runtime.h>
#include <math.h>
#include <stdint.h>

// Problem constants (fixed by the dataset)
#define SD 5
#define OD 32
#define NB 256
#define TT 8192

// ---------------- scratch (device globals; allocation-free) ----------------
__device__ float g_proj[TT * 6 * NB];      // [(t*6+k)*NB+b]
__device__ float g_J[TT * 26];             // [t*26+e], e=25 -> logdetS
__device__ float g_U[25];
__device__ float g_llpart[NB * 128];       // [b][chunk]

// ---------------- Riccati config ----------------
#define R_LR 8
#define R_WR 24
#define R_NBLK 32                   // 1024 chunks

// ---------------- projection config (persistent, cp.async pipelined) -------
#define PP_NBLK 444                 // 3 blocks/SM x 148 SMs
#define TROWB 128                   // 32 floats, unpadded, XOR-swizzled
#define TILEB (NB * TROWB)          // 32768 B per tile
#define P_SMEM (2 * TILEB)          // 65536 B double buffer

// ---------------- z-recursion + covs-broadcast config ----------------
#define Z_L 64
#define Z_W 48
#define Z_NCHUNK (TT / Z_L)         // 128
#define Z_MAXSTEPS (Z_L + Z_W)      // 112
#define BC_TILE 32
#define BC_NBLK (TT / BC_TILE)      // 256
#define ZB_SMEM (Z_MAXSTEPS * 26 * 4 + NB * 41 * 4)   // 53632 B

// output offsets (tuple flattened: states, covs, ll)
#define OUT_STATES 0
#define OUT_COVS   ((size_t)NB * TT * SD)
#define OUT_LL     (OUT_COVS + (size_t)NB * TT * SD * SD)

// ---------------- f32x2 packed-math helpers ----------------
__device__ __forceinline__ unsigned long long f2fma(
    unsigned long long a, unsigned long long b, unsigned long long c) {
    unsigned long long d;
    asm("fma.rn.f32x2 %0, %1, %2, %3;" : "=l"(d) : "l"(a), "l"(b), "l"(c));
    return d;
}
__device__ __forceinline__ unsigned long long f2mul(
    unsigned long long a, unsigned long long b) {
    unsigned long long d;
    asm("mul.rn.f32x2 %0, %1, %2;" : "=l"(d) : "l"(a), "l"(b));
    return d;
}
__device__ __forceinline__ unsigned long long pack2(float lo, float hi) {
    unsigned long long d;
    asm("mov.b64 %0, {%1, %2};" : "=l"(d) : "f"(lo), "f"(hi));
    return d;
}
__device__ __forceinline__ float2 unpack2(unsigned long long v) {
    float2 r;
    asm("mov.b64 {%0, %1}, %2;" : "=f"(r.x), "=f"(r.y) : "l"(v));
    return r;
}

// ============================================================================
// Kernel 1: data-independent Riccati recursion -> g_J, g_U
// ============================================================================
__global__ __launch_bounds__(32) void k_ricc(
    const float* __restrict__ Ain,
    const float* __restrict__ Cin,
    const float* __restrict__ Qlog,
    const float* __restrict__ Rlog)
{
    const int chunk = blockIdx.x * 32 + threadIdx.x;

    float a[25];
    #pragma unroll
    for (int i = 0; i < 25; i++) a[i] = Ain[i];
    float q[5];
    #pragma unroll
    for (int k = 0; k < 5; k++) q[k] = expf(Qlog[k]);

    float U[25];
    #pragma unroll
    for (int i = 0; i < 25; i++) U[i] = 0.f;
    float logdetR = 0.f;
    for (int o = 0; o < OD; o++) {
        float rl = Rlog[o];
        logdetR += rl;
        float ri = expf(-rl);
        float cv[5];
        #pragma unroll
        for (int k = 0; k < 5; k++) cv[k] = Cin[o * 5 + k];
        #pragma unroll
        for (int i = 0; i < 5; i++) {
            float f = ri * cv[i];
            #pragma unroll
            for (int j = 0; j < 5; j++) U[i * 5 + j] += f * cv[j];
        }
    }
    if (chunk == 0) {
        #pragma unroll
        for (int i = 0; i < 25; i++) g_U[i] = U[i];
    }

    const int town = chunk * R_LR;
    const int tend = town + R_LR;
    int t0s = town - R_WR; if (t0s < 0) t0s = 0;

    float P[25];
    #pragma unroll
    for (int i = 0; i < 25; i++) P[i] = (i % 6 == 0) ? 1.f : 0.f;

    for (int t = t0s; t < tend; ++t) {
        float Tm[25], Pp[25];
        #pragma unroll
        for (int i = 0; i < 5; i++)
            #pragma unroll
            for (int j = 0; j < 5; j++) {
                float s = 0.f;
                #pragma unroll
                for (int k = 0; k < 5; k++) s += a[i * 5 + k] * P[k * 5 + j];
                Tm[i * 5 + j] = s;
            }
        #pragma unroll
        for (int i = 0; i < 5; i++)
            #pragma unroll
            for (int j = 0; j < 5; j++) {
                float s = 0.f;
                #pragma unroll
                for (int k = 0; k < 5; k++) s += Tm[i * 5 + k] * a[j * 5 + k];
                Pp[i * 5 + j] = s;
            }
        #pragma unroll
        for (int i = 0; i < 5; i++) Pp[i * 5 + i] += q[i];

        float M[25], V[25];
        #pragma unroll
        for (int i = 0; i < 5; i++)
            #pragma unroll
            for (int j = 0; j < 5; j++) {
                float s = (i == j) ? 1.f : 0.f;
                #pragma unroll
                for (int k = 0; k < 5; k++) s += U[i * 5 + k] * Pp[k * 5 + j];
                M[i * 5 + j] = s;
            }
        #pragma unroll
        for (int i = 0; i < 25; i++) V[i] = (i % 6 == 0) ? 1.f : 0.f;
        float det = 1.f;
        #pragma unroll
        for (int k = 0; k < 5; k++) {
            float piv = M[k * 5 + k];
            det *= piv;
            float ip = 1.f / piv;
            #pragma unroll
            for (int j = 0; j < 5; j++) { M[k * 5 + j] *= ip; V[k * 5 + j] *= ip; }
            #pragma unroll
            for (int i2 = 0; i2 < 5; i2++) {
                if (i2 == k) continue;
                float f = M[i2 * 5 + k];
                #pragma unroll
                for (int j = 0; j < 5; j++) {
                    M[i2 * 5 + j] -= f * M[k * 5 + j];
                    V[i2 * 5 + j] -= f * V[k * 5 + j];
                }
            }
        }
        #pragma unroll
        for (int i = 0; i < 5; i++)
            #pragma unroll
            for (int j = 0; j < 5; j++) {
                float s = 0.f;
                #pragma unroll
                for (int k = 0; k < 5; k++) s += Pp[i * 5 + k] * V[k * 5 + j];
                P[i * 5 + j] = s;
            }

        if (t >= town) {
            float ld = logdetR + logf(det);
            #pragma unroll
            for (int e = 0; e < 25; e++) g_J[t * 26 + e] = P[e];
            g_J[t * 26 + 25] = ld;
        }
    }
}

// ---------------- cp.async helpers ----------------
__device__ __forceinline__ void cp16(uint32_t saddr, const void* gaddr) {
    asm volatile("cp.async.cg.shared.global [%0], [%1], 16;"
                 :: "r"(saddr), "l"(gaddr));
}
#define CP_COMMIT() asm volatile("cp.async.commit_group;" ::: "memory")
#define CP_WAIT1()  asm volatile("cp.async.wait_group 1;" ::: "memory")

// XOR swizzle: 16B chunk q of row b goes to chunk q ^ (b & 7)
__device__ __forceinline__ uint32_t sw_off(int b, int q) {
    return (uint32_t)(b * TROWB + ((q ^ (b & 7)) << 4));
}

// ============================================================================
// Kernel 2: observation projection y -> g_proj   (persistent + f32x2)
// Constants pre-paired per o-pair: 3x LDS.128 + 7 packed FMA per pair.
// ============================================================================
__global__ __launch_bounds__(256) void k_proj(
    const float* __restrict__ y,
    const float* __restrict__ Cin,
    const float* __restrict__ Rlog)
{
    extern __shared__ float sy[];            // [2][NB][32] swizzled
    __shared__ ulonglong2 ppu[48];           // [16 o-pairs][3]
    const int tid = threadIdx.x;

    if (tid < 16) {
        float* ppf = (float*)ppu;
        int o0 = 2 * tid, o1 = o0 + 1;
        float r0 = expf(-Rlog[o0]);
        float r1 = expf(-Rlog[o1]);
        #pragma unroll
        for (int k = 0; k < 5; k++) {
            ppf[tid * 12 + 2 * k + 0] = Cin[o0 * 5 + k] * r0;
            ppf[tid * 12 + 2 * k + 1] = Cin[o1 * 5 + k] * r1;
        }
        ppf[tid * 12 + 10] = r0;
        ppf[tid * 12 + 11] = r1;
    }
    __syncthreads();

    const uint32_t sbase = (uint32_t)__cvta_generic_to_shared(sy);
    const char* yb = (const char*)y;

    int t = blockIdx.x;
    int buf = 0;

    // prologue: load tile t into buf 0
    {
        #pragma unroll
        for (int it = 0; it < 8; ++it) {
            int f = it * 256 + tid;
            int b = f >> 3, q = f & 7;
            cp16(sbase + sw_off(b, q),
                 yb + ((size_t)b * TT + t) * 128 + q * 16);
        }
        CP_COMMIT();
    }

    while (t < TT) {
        const int tn = t + PP_NBLK;
        if (tn < TT) {
            #pragma unroll
            for (int it = 0; it < 8; ++it) {
                int f = it * 256 + tid;
                int b = f >> 3, q = f & 7;
                cp16(sbase + (1 - buf) * TILEB + sw_off(b, q),
                     yb + ((size_t)b * TT + tn) * 128 + q * 16);
            }
        }
        CP_COMMIT();
        CP_WAIT1();
        __syncthreads();

        // compute: thread = batch row b, obs pairs packed f32x2
        const int b = tid;
        const float* base = sy + (buf * TILEB) / 4;
        unsigned long long yv2[16];
        #pragma unroll
        for (int q = 0; q < 8; q++) {
            const float4 x = *(const float4*)((const char*)base + sw_off(b, q));
            yv2[2 * q + 0] = pack2(x.x, x.y);
            yv2[2 * q + 1] = pack2(x.z, x.w);
        }
        unsigned long long c0 = 0, c1 = 0, c2 = 0, c3 = 0, c4 = 0, sy2 = 0;
        #pragma unroll
        for (int op = 0; op < 16; op++) {
            ulonglong2 l0 = ppu[op * 3 + 0];   // c0 | c1 pairs
            ulonglong2 l1 = ppu[op * 3 + 1];   // c2 | c3 pairs
            ulonglong2 l2 = ppu[op * 3 + 2];   // c4 | rin pairs
            unsigned long long yv = yv2[op];
            c0 = f2fma(l0.x, yv, c0);
            c1 = f2fma(l0.y, yv, c1);
            c2 = f2fma(l1.x, yv, c2);
            c3 = f2fma(l1.y, yv, c3);
            c4 = f2fma(l2.x, yv, c4);
            unsigned long long ry = f2mul(l2.y, yv);
            sy2 = f2fma(ry, yv, sy2);
        }
        float2 u0 = unpack2(c0), u1 = unpack2(c1), u2 = unpack2(c2);
        float2 u3 = unpack2(c3), u4 = unpack2(c4), us = unpack2(sy2);

        float* pd = &g_proj[((size_t)t * 6) * NB + b];
        pd[0 * NB] = u0.x + u0.y;
        pd[1 * NB] = u1.x + u1.y;
        pd[2 * NB] = u2.x + u2.y;
        pd[3 * NB] = u3.x + u3.y;
        pd[4 * NB] = u4.x + u4.y;
        pd[5 * NB] = us.x + us.y;

        __syncthreads();
        buf ^= 1;
        t = tn;
    }
}

// ---------------- one z step ----------------
#define Z_STEP(CCBUF, U_)                                                     \
    {                                                                         \
        float zp[5];                                                          \
        _Pragma("unroll")                                                     \
        for (int i = 0; i < 5; i++)                                           \
            zp[i] = a[i*5+0]*z0 + a[i*5+1]*z1 + a[i*5+2]*z2                   \
                  + a[i*5+3]*z3 + a[i*5+4]*z4;                                \
        float g[5];                                                           \
        _Pragma("unroll")                                                     \
        for (int i = 0; i < 5; i++) {                                         \
            float sa = 0.f;                                                   \
            _Pragma("unroll")                                                 \
            for (int j = 0; j < 5; j++) sa += U_[i*5+j] * zp[j];              \
            g[i] = sa;                                                        \
        }                                                                     \
        float w[5];                                                           \
        _Pragma("unroll")                                                     \
        for (int i = 0; i < 5; i++) w[i] = (CCBUF)[i] - g[i];                 \
        const float* Jr = &sJ[s * 26];                                        \
        float h[5];                                                           \
        _Pragma("unroll")                                                     \
        for (int i = 0; i < 5; i++) {                                         \
            float sa = 0.f;                                                   \
            _Pragma("unroll")                                                 \
            for (int j = 0; j < 5; j++) sa += Jr[i*5+j] * w[j];               \
            h[i] = sa;                                                        \
        }                                                                     \
        z0 = zp[0]+h[0]; z1 = zp[1]+h[1]; z2 = zp[2]+h[2];                    \
        z3 = zp[3]+h[3]; z4 = zp[4]+h[4];                                     \
        if (s >= warm) {                                                      \
            float cz = 0, zg = 0, wh = 0;                                     \
            _Pragma("unroll")                                                 \
            for (int i = 0; i < 5; i++) {                                     \
                cz += (CCBUF)[i]*zp[i]; zg += zp[i]*g[i]; wh += w[i]*h[i];    \
            }                                                                 \
            float quad = (CCBUF)[5] - 2.f*cz + zg - wh;                       \
            ll -= 0.5f * ((float)OD * 1.8378770664093453f                     \
                          + Jr[25] + quad);                                   \
            int sl = (s - warm) & 7;                                          \
            float* sb = &sbuf[b * 41 + sl * 5];                               \
            sb[0]=z0; sb[1]=z1; sb[2]=z2; sb[3]=z3; sb[4]=z4;                 \
        }                                                                     \
    }

// ============================================================================
// Kernel 3: fused  (a) z-recursion + states + ll partials [blocks 0..127]
//                  (b) covariance broadcast J -> covs     [blocks 128..383]
// ============================================================================
__global__ __launch_bounds__(256) void k_zbc(
    const float* __restrict__ Ain, float* __restrict__ out)
{
    extern __shared__ float sm[];
    const int tid = threadIdx.x;

    if (blockIdx.x < Z_NCHUNK) {
        float* sJ   = sm;                         // [Z_MAXSTEPS][26]
        float* sbuf = sm + Z_MAXSTEPS * 26;       // [NB][41]

        const int chunk = blockIdx.x;
        const int town = chunk * Z_L;
        int t0 = town - Z_W; if (t0 < 0) t0 = 0;
        const int nsteps = town + Z_L - t0;       // 64 or 112 (both %8==0)
        const int warm = town - t0;               // 0 or 48

        for (int i = tid; i < nsteps * 26; i += 256) sJ[i] = g_J[t0 * 26 + i];
        __syncthreads();

        float a[25], U[25];
        #pragma unroll
        for (int i = 0; i < 25; i++) { a[i] = Ain[i]; U[i] = g_U[i]; }

        float z0 = 0, z1 = 0, z2 = 0, z3 = 0, z4 = 0;
        float ll = 0.f;
        const int b = tid;
        const float* pbase = &g_proj[(size_t)t0 * 6 * NB + b];

        float bufA[4][6], bufB[4][6];
        #pragma unroll
        for (int u = 0; u < 4; u++)
            #pragma unroll
            for (int k = 0; k < 6; k++)
                bufA[u][k] = pbase[((size_t)u * 6 + k) * NB];

        for (int s8 = 0; s8 < nsteps; s8 += 8) {
            if (s8 + 4 < nsteps) {
                const float* pn = pbase + (size_t)(s8 + 4) * 6 * NB;
                #pragma unroll
                for (int u = 0; u < 4; u++)
                    #pragma unroll
                    for (int k = 0; k < 6; k++)
                        bufB[u][k] = pn[((size_t)u * 6 + k) * NB];
            }
            #pragma unroll
            for (int u = 0; u < 4; u++) {
                const int s = s8 + u;
                Z_STEP(bufA[u], U)
            }
            if (s8 + 8 < nsteps) {
                const float* pn = pbase + (size_t)(s8 + 8) * 6 * NB;
                #pragma unroll
                for (int u = 0; u < 4; u++)
                    #pragma unroll
                    for (int k = 0; k < 6; k++)
                        bufA[u][k] = pn[((size_t)u * 6 + k) * NB];
            }
            #pragma unroll
            for (int u = 0; u < 4; u++) {
                const int s = s8 + 4 + u;
                Z_STEP(bufB[u], U)
            }
            if (s8 >= warm) {
                __syncthreads();
                const int tflush0 = town + (s8 - warm);
                for (int f = tid; f < NB * 40; f += 256) {
                    int bb = f / 40;
                    int u  = f % 40;
                    __stcs(&out[OUT_STATES + ((size_t)bb * TT + tflush0) * 5 + u],
                           sbuf[bb * 41 + u]);
                }
                __syncthreads();
            }
        }
        g_llpart[(size_t)b * Z_NCHUNK + chunk] = ll;
    } else {
        // ---- covariance broadcast: contiguous float4 streaming stores ----
        const int v = blockIdx.x - Z_NCHUNK;       // 0..255
        const int t0 = v * BC_TILE;
        float* sJ = sm;                            // 800 floats
        for (int i = tid; i < BC_TILE * 25; i += 256) {
            int tt = i / 25;
            int e  = i % 25;
            sJ[i] = g_J[(t0 + tt) * 26 + e];
        }
        __syncthreads();
        const float4* sJ4 = (const float4*)sJ;     // 200 float4
        float4* out4 = (float4*)(out + OUT_COVS);
        const unsigned base = (unsigned)v * 200u;
        if (tid < 200) {
            float4 val = sJ4[tid];
            #pragma unroll 4
            for (int bb = 0; bb < NB; ++bb) {
                __stcs(&out4[(size_t)bb * (TT * 25 / 4) + base + tid], val);
            }
        }
    }
}

// ============================================================================
// Kernel 4: ll reduction — block = one batch, 32 lanes, butterfly reduce
// ============================================================================
__global__ __launch_bounds__(32) void k_ll(float* __restrict__ out)
{
    const int b = blockIdx.x;
    const int lane = threadIdx.x;
    const float* p = &g_llpart[(size_t)b * Z_NCHUNK];
    float s = 0.f;
    #pragma unroll
    for (int k = 0; k < Z_NCHUNK / 32; k++) s += p[lane + k * 32];
    #pragma unroll
    for (int d = 16; d >= 1; d >>= 1)
        s += __shfl_xor_sync(0xFFFFFFFFu, s, d);
    if (lane == 0) out[OUT_LL + b] = s;
}

// ============================================================================
extern "C" void kernel_launch(void* const* d_in, const int* in_sizes, int n_in,
                              void* d_out, int out_size)
{
    const float* y  = (const float*)d_in[0];
    const float* A  = (const float*)d_in[1];
    const float* C  = (const float*)d_in[2];
    const float* Ql = (const float*)d_in[3];
    const float* Rl = (const float*)d_in[4];
    float* out = (float*)d_out;

    cudaFuncSetAttribute(k_proj, cudaFuncAttributeMaxDynamicSharedMemorySize, P_SMEM);
    cudaFuncSetAttribute(k_zbc, cudaFuncAttributeMaxDynamicSharedMemorySize, ZB_SMEM);

    k_ricc<<<R_NBLK, 32>>>(A, C, Ql, Rl);
    k_proj<<<PP_NBLK, 256, P_SMEM>>>(y, C, Rl);
    k_zbc<<<Z_NCHUNK + BC_NBLK, 256, ZB_SMEM>>>(A, out);
    k_ll<<<NB, 32>>>(out);
}

// round 10
// speedup vs baseline: 1.0586x; 1.0586x over previous
#include <cuda_runtime.h>
#include <math.h>
#include <stdint.h>

// Problem constants (fixed by the dataset)
#define SD 5
#define OD 32
#define NB 256
#define TT 8192

// ---------------- scratch (device globals; allocation-free) ----------------
__device__ float g_proj[TT * 6 * NB];      // [(t*6+k)*NB+b]
__device__ float g_J[TT * 26];             // [t*26+e], e=25 -> logdetS
__device__ float g_U[25];
__device__ float g_llpart[NB * 256];       // [b][chunk]

// ---------------- Riccati config ----------------
#define R_LR 8
#define R_WR 24
#define R_NBLK 32                   // 1024 chunks

// ---------------- projection config (persistent, cp.async pipelined) -------
#define PP_NBLK 444                 // 3 blocks/SM x 148 SMs
#define TROWB 128                   // 32 floats, unpadded, XOR-swizzled
#define TILEB (NB * TROWB)          // 32768 B per tile
#define P_SMEM (2 * TILEB)          // 65536 B double buffer

// ---------------- covs broadcast (interleaved into proj blocks) ------------
#define BC_ST 16                    // t's per BC subtile
#define BC_NST (TT / BC_ST)         // 512 subtiles
#define COVS_STRIDE4 (TT * 25 / 4)  // 51200 float4 per batch

// ---------------- z-recursion config (R8-validated) ----------------
#define Z_L 32
#define Z_W 48
#define Z_NCHUNK (TT / Z_L)         // 256
#define Z_MAXSTEPS (Z_L + Z_W)      // 80
#define Z_SMEM (Z_MAXSTEPS * 26 * 4 + NB * 41 * 4)   // 50304 B

// output offsets (tuple flattened: states, covs, ll)
#define OUT_STATES 0
#define OUT_COVS   ((size_t)NB * TT * SD)
#define OUT_LL     (OUT_COVS + (size_t)NB * TT * SD * SD)

// ============================================================================
// Kernel 1: data-independent Riccati recursion -> g_J, g_U
// ============================================================================
__global__ __launch_bounds__(32) void k_ricc(
    const float* __restrict__ Ain,
    const float* __restrict__ Cin,
    const float* __restrict__ Qlog,
    const float* __restrict__ Rlog)
{
    const int chunk = blockIdx.x * 32 + threadIdx.x;

    float a[25];
    #pragma unroll
    for (int i = 0; i < 25; i++) a[i] = Ain[i];
    float q[5];
    #pragma unroll
    for (int k = 0; k < 5; k++) q[k] = expf(Qlog[k]);

    float U[25];
    #pragma unroll
    for (int i = 0; i < 25; i++) U[i] = 0.f;
    float logdetR = 0.f;
    for (int o = 0; o < OD; o++) {
        float rl = Rlog[o];
        logdetR += rl;
        float ri = expf(-rl);
        float cv[5];
        #pragma unroll
        for (int k = 0; k < 5; k++) cv[k] = Cin[o * 5 + k];
        #pragma unroll
        for (int i = 0; i < 5; i++) {
            float f = ri * cv[i];
            #pragma unroll
            for (int j = 0; j < 5; j++) U[i * 5 + j] += f * cv[j];
        }
    }
    if (chunk == 0) {
        #pragma unroll
        for (int i = 0; i < 25; i++) g_U[i] = U[i];
    }

    const int town = chunk * R_LR;
    const int tend = town + R_LR;
    int t0s = town - R_WR; if (t0s < 0) t0s = 0;

    float P[25];
    #pragma unroll
    for (int i = 0; i < 25; i++) P[i] = (i % 6 == 0) ? 1.f : 0.f;

    for (int t = t0s; t < tend; ++t) {
        float Tm[25], Pp[25];
        #pragma unroll
        for (int i = 0; i < 5; i++)
            #pragma unroll
            for (int j = 0; j < 5; j++) {
                float s = 0.f;
                #pragma unroll
                for (int k = 0; k < 5; k++) s += a[i * 5 + k] * P[k * 5 + j];
                Tm[i * 5 + j] = s;
            }
        #pragma unroll
        for (int i = 0; i < 5; i++)
            #pragma unroll
            for (int j = 0; j < 5; j++) {
                float s = 0.f;
                #pragma unroll
                for (int k = 0; k < 5; k++) s += Tm[i * 5 + k] * a[j * 5 + k];
                Pp[i * 5 + j] = s;
            }
        #pragma unroll
        for (int i = 0; i < 5; i++) Pp[i * 5 + i] += q[i];

        float M[25], V[25];
        #pragma unroll
        for (int i = 0; i < 5; i++)
            #pragma unroll
            for (int j = 0; j < 5; j++) {
                float s = (i == j) ? 1.f : 0.f;
                #pragma unroll
                for (int k = 0; k < 5; k++) s += U[i * 5 + k] * Pp[k * 5 + j];
                M[i * 5 + j] = s;
            }
        #pragma unroll
        for (int i = 0; i < 25; i++) V[i] = (i % 6 == 0) ? 1.f : 0.f;
        float det = 1.f;
        #pragma unroll
        for (int k = 0; k < 5; k++) {
            float piv = M[k * 5 + k];
            det *= piv;
            float ip = 1.f / piv;
            #pragma unroll
            for (int j = 0; j < 5; j++) { M[k * 5 + j] *= ip; V[k * 5 + j] *= ip; }
            #pragma unroll
            for (int i2 = 0; i2 < 5; i2++) {
                if (i2 == k) continue;
                float f = M[i2 * 5 + k];
                #pragma unroll
                for (int j = 0; j < 5; j++) {
                    M[i2 * 5 + j] -= f * M[k * 5 + j];
                    V[i2 * 5 + j] -= f * V[k * 5 + j];
                }
            }
        }
        #pragma unroll
        for (int i = 0; i < 5; i++)
            #pragma unroll
            for (int j = 0; j < 5; j++) {
                float s = 0.f;
                #pragma unroll
                for (int k = 0; k < 5; k++) s += Pp[i * 5 + k] * V[k * 5 + j];
                P[i * 5 + j] = s;
            }

        if (t >= town) {
            float ld = logdetR + logf(det);
            #pragma unroll
            for (int e = 0; e < 25; e++) g_J[t * 26 + e] = P[e];
            g_J[t * 26 + 25] = ld;
        }
    }
}

// ---------------- cp.async helpers ----------------
__device__ __forceinline__ void cp16(uint32_t saddr, const void* gaddr) {
    asm volatile("cp.async.cg.shared.global [%0], [%1], 16;"
                 :: "r"(saddr), "l"(gaddr));
}
#define CP_COMMIT() asm volatile("cp.async.commit_group;" ::: "memory")
#define CP_WAIT1()  asm volatile("cp.async.wait_group 1;" ::: "memory")

// XOR swizzle: 16B chunk q of row b goes to chunk q ^ (b & 7)
__device__ __forceinline__ uint32_t sw_off(int b, int q) {
    return (uint32_t)(b * TROWB + ((q ^ (b & 7)) << 4));
}

// ============================================================================
// Kernel 2: persistent proj (y -> g_proj) WITH interleaved covs broadcast.
// 444 persistent blocks, double-buffered cp.async tiles (one t x 256 b).
// During iterations 0..1 each block also claims BC subtile
// st = iter*444 + blockIdx.x (<512) and streams J -> covs (210MB), filling
// the HBM pipe alongside the y read.
// ============================================================================
__global__ __launch_bounds__(256) void k_proj(
    const float* __restrict__ y,
    const float* __restrict__ Cin,
    const float* __restrict__ Rlog,
    float* __restrict__ out)
{
    extern __shared__ float sy[];            // [2][NB][32] swizzled
    __shared__ float pp[OD * 8];             // {crv0..4, rin, 0, 0} per o
    __shared__ float sJb[BC_ST * 25];        // 400 floats BC staging
    const int tid = threadIdx.x;

    if (tid < OD) {
        float ri = expf(-Rlog[tid]);
        #pragma unroll
        for (int k = 0; k < 5; k++) pp[tid * 8 + k] = Cin[tid * 5 + k] * ri;
        pp[tid * 8 + 5] = ri;
        pp[tid * 8 + 6] = 0.f;
        pp[tid * 8 + 7] = 0.f;
    }
    __syncthreads();

    const uint32_t sbase = (uint32_t)__cvta_generic_to_shared(sy);
    const char* yb = (const char*)y;

    int t = blockIdx.x;
    int buf = 0;
    int iter = 0;

    // prologue: load tile t into buf 0
    {
        #pragma unroll
        for (int it = 0; it < 8; ++it) {
            int f = it * 256 + tid;
            int b = f >> 3, q = f & 7;
            cp16(sbase + sw_off(b, q),
                 yb + ((size_t)b * TT + t) * 128 + q * 16);
        }
        CP_COMMIT();
    }

    while (t < TT) {
        const int tn = t + PP_NBLK;
        if (tn < TT) {
            #pragma unroll
            for (int it = 0; it < 8; ++it) {
                int f = it * 256 + tid;
                int b = f >> 3, q = f & 7;
                cp16(sbase + (1 - buf) * TILEB + sw_off(b, q),
                     yb + ((size_t)b * TT + tn) * 128 + q * 16);
            }
        }
        CP_COMMIT();
        CP_WAIT1();
        __syncthreads();

        // ---- proj compute: thread = batch row b ----
        const int b = tid;
        const float* base = sy + (buf * TILEB) / 4;
        float v[OD];
        #pragma unroll
        for (int q = 0; q < 8; q++) {
            const float4 x = *(const float4*)((const char*)base + sw_off(b, q));
            v[q * 4 + 0] = x.x; v[q * 4 + 1] = x.y;
            v[q * 4 + 2] = x.z; v[q * 4 + 3] = x.w;
        }
        float c0 = 0, c1 = 0, c2 = 0, c3 = 0, c4 = 0, syy = 0;
        const float4* p4 = (const float4*)pp;
        #pragma unroll
        for (int o = 0; o < OD; o++) {
            float4 pa = p4[o * 2];
            float4 pb = p4[o * 2 + 1];
            float yv = v[o];
            c0 += pa.x * yv;
            c1 += pa.y * yv;
            c2 += pa.z * yv;
            c3 += pa.w * yv;
            c4 += pb.x * yv;
            syy += (pb.y * yv) * yv;
        }
        float* pd = &g_proj[((size_t)t * 6) * NB + b];
        pd[0 * NB] = c0; pd[1 * NB] = c1; pd[2 * NB] = c2;
        pd[3 * NB] = c3; pd[4 * NB] = c4; pd[5 * NB] = syy;

        // ---- interleaved covs broadcast (first two iterations only) ----
        const int st = iter * PP_NBLK + blockIdx.x;
        if (st < BC_NST) {
            // stage 16 t's of J (400 floats) into smem, packed t*25+e
            for (int i = tid; i < BC_ST * 25; i += 256) {
                int tt = i / 25;
                int e  = i % 25;
                sJb[i] = g_J[(st * BC_ST + tt) * 26 + e];
            }
            __syncthreads();
            const float4* sJ4 = (const float4*)sJb;   // 100 float4
            float4* out4 = (float4*)(out + OUT_COVS);
            const unsigned base4 = (unsigned)st * 100u;
            if (tid < 100) {
                float4 val = sJ4[tid];
                #pragma unroll 4
                for (int bb = 0; bb < NB; ++bb) {
                    __stcs(&out4[(size_t)bb * COVS_STRIDE4 + base4 + tid], val);
                }
            }
        }

        __syncthreads();       // buffer reuse + sJb reuse barrier
        buf ^= 1;
        t = tn;
        iter++;
    }
}

// ---------------- one z step ----------------
#define Z_STEP(CCBUF, U_)                                                     \
    {                                                                         \
        float zp[5];                                                          \
        _Pragma("unroll")                                                     \
        for (int i = 0; i < 5; i++)                                           \
            zp[i] = a[i*5+0]*z0 + a[i*5+1]*z1 + a[i*5+2]*z2                   \
                  + a[i*5+3]*z3 + a[i*5+4]*z4;                                \
        float g[5];                                                           \
        _Pragma("unroll")                                                     \
        for (int i = 0; i < 5; i++) {                                         \
            float sa = 0.f;                                                   \
            _Pragma("unroll")                                                 \
            for (int j = 0; j < 5; j++) sa += U_[i*5+j] * zp[j];              \
            g[i] = sa;                                                        \
        }                                                                     \
        float w[5];                                                           \
        _Pragma("unroll")                                                     \
        for (int i = 0; i < 5; i++) w[i] = (CCBUF)[i] - g[i];                 \
        const float* Jr = &sJ[s * 26];                                        \
        float h[5];                                                           \
        _Pragma("unroll")                                                     \
        for (int i = 0; i < 5; i++) {                                         \
            float sa = 0.f;                                                   \
            _Pragma("unroll")                                                 \
            for (int j = 0; j < 5; j++) sa += Jr[i*5+j] * w[j];               \
            h[i] = sa;                                                        \
        }                                                                     \
        z0 = zp[0]+h[0]; z1 = zp[1]+h[1]; z2 = zp[2]+h[2];                    \
        z3 = zp[3]+h[3]; z4 = zp[4]+h[4];                                     \
        if (s >= warm) {                                                      \
            float cz = 0, zg = 0, wh = 0;                                     \
            _Pragma("unroll")                                                 \
            for (int i = 0; i < 5; i++) {                                     \
                cz += (CCBUF)[i]*zp[i]; zg += zp[i]*g[i]; wh += w[i]*h[i];    \
            }                                                                 \
            float quad = (CCBUF)[5] - 2.f*cz + zg - wh;                       \
            ll -= 0.5f * ((float)OD * 1.8378770664093453f                     \
                          + Jr[25] + quad);                                   \
            int sl = (s - warm) & 7;                                          \
            float* sb = &sbuf[b * 41 + sl * 5];                               \
            sb[0]=z0; sb[1]=z1; sb[2]=z2; sb[3]=z3; sb[4]=z4;                 \
        }                                                                     \
    }

// ============================================================================
// Kernel 3: z-recursion + states + ll partials (256 chunks, z-only)
// ============================================================================
__global__ __launch_bounds__(256) void k_z(
    const float* __restrict__ Ain, float* __restrict__ out)
{
    extern __shared__ float sm[];
    const int tid = threadIdx.x;
    float* sJ   = sm;                         // [Z_MAXSTEPS][26]
    float* sbuf = sm + Z_MAXSTEPS * 26;       // [NB][41]

    const int chunk = blockIdx.x;
    const int town = chunk * Z_L;
    int t0 = town - Z_W; if (t0 < 0) t0 = 0;
    const int nsteps = town + Z_L - t0;       // 32 or 80 (both %8==0)
    const int warm = town - t0;               // 0 or 48

    for (int i = tid; i < nsteps * 26; i += 256) sJ[i] = g_J[t0 * 26 + i];
    __syncthreads();

    float a[25], U[25];
    #pragma unroll
    for (int i = 0; i < 25; i++) { a[i] = Ain[i]; U[i] = g_U[i]; }

    float z0 = 0, z1 = 0, z2 = 0, z3 = 0, z4 = 0;
    float ll = 0.f;
    const int b = tid;
    const float* pbase = &g_proj[(size_t)t0 * 6 * NB + b];

    float bufA[4][6], bufB[4][6];
    #pragma unroll
    for (int u = 0; u < 4; u++)
        #pragma unroll
        for (int k = 0; k < 6; k++)
            bufA[u][k] = pbase[((size_t)u * 6 + k) * NB];

    for (int s8 = 0; s8 < nsteps; s8 += 8) {
        if (s8 + 4 < nsteps) {
            const float* pn = pbase + (size_t)(s8 + 4) * 6 * NB;
            #pragma unroll
            for (int u = 0; u < 4; u++)
                #pragma unroll
                for (int k = 0; k < 6; k++)
                    bufB[u][k] = pn[((size_t)u * 6 + k) * NB];
        }
        #pragma unroll
        for (int u = 0; u < 4; u++) {
            const int s = s8 + u;
            Z_STEP(bufA[u], U)
        }
        if (s8 + 8 < nsteps) {
            const float* pn = pbase + (size_t)(s8 + 8) * 6 * NB;
            #pragma unroll
            for (int u = 0; u < 4; u++)
                #pragma unroll
                for (int k = 0; k < 6; k++)
                    bufA[u][k] = pn[((size_t)u * 6 + k) * NB];
        }
        #pragma unroll
        for (int u = 0; u < 4; u++) {
            const int s = s8 + 4 + u;
            Z_STEP(bufB[u], U)
        }
        if (s8 >= warm) {
            __syncthreads();
            const int tflush0 = town + (s8 - warm);
            for (int f = tid; f < NB * 40; f += 256) {
                int bb = f / 40;
                int u  = f % 40;
                __stcs(&out[OUT_STATES + ((size_t)bb * TT + tflush0) * 5 + u],
                       sbuf[bb * 41 + u]);
            }
            __syncthreads();
        }
    }
    g_llpart[(size_t)b * Z_NCHUNK + chunk] = ll;
}

// ============================================================================
// Kernel 4: ll reduction — block = one batch, 32 lanes, butterfly reduce
// ============================================================================
__global__ __launch_bounds__(32) void k_ll(float* __restrict__ out)
{
    const int b = blockIdx.x;
    const int lane = threadIdx.x;
    const float* p = &g_llpart[(size_t)b * Z_NCHUNK];
    float s = 0.f;
    #pragma unroll
    for (int k = 0; k < Z_NCHUNK / 32; k++) s += p[lane + k * 32];
    #pragma unroll
    for (int d = 16; d >= 1; d >>= 1)
        s += __shfl_xor_sync(0xFFFFFFFFu, s, d);
    if (lane == 0) out[OUT_LL + b] = s;
}

// ============================================================================
extern "C" void kernel_launch(void* const* d_in, const int* in_sizes, int n_in,
                              void* d_out, int out_size)
{
    const float* y  = (const float*)d_in[0];
    const float* A  = (const float*)d_in[1];
    const float* C  = (const float*)d_in[2];
    const float* Ql = (const float*)d_in[3];
    const float* Rl = (const float*)d_in[4];
    float* out = (float*)d_out;

    cudaFuncSetAttribute(k_proj, cudaFuncAttributeMaxDynamicSharedMemorySize, P_SMEM);
    cudaFuncSetAttribute(k_z, cudaFuncAttributeMaxDynamicSharedMemorySize, Z_SMEM);

    k_ricc<<<R_NBLK, 32>>>(A, C, Ql, Rl);
    k_proj<<<PP_NBLK, 256, P_SMEM>>>(y, C, Rl, out);
    k_z<<<Z_NCHUNK, 256, Z_SMEM>>>(A, out);
    k_ll<<<NB, 32>>>(out);
}

// round 11
// speedup vs baseline: 1.1292x; 1.0668x over previous
#include <cuda_runtime.h>
#include <math.h>
#include <stdint.h>

// Problem constants (fixed by the dataset)
#define SD 5
#define OD 32
#define NB 256
#define TT 8192

// ---------------- scratch (device globals; allocation-free) ----------------
__device__ float g_proj[TT * 6 * NB];      // [(t*6+k)*NB+b]
__device__ float g_J[TT * 26];             // [t*26+e], e=25 -> logdetS
__device__ float g_U[25];
__device__ float g_llpart[NB * 256];       // [b][chunk]

// ---------------- Riccati config ----------------
#define R_LR 8
#define R_WR 24
#define R_NBLK 32                   // 1024 chunks

// ---------------- projection config (persistent, 4-stage cp.async ring) ----
#define PP_NBLK 148                 // 1 block/SM
#define TROWB 128                   // 32 floats, unpadded, XOR-swizzled
#define TILEB (NB * TROWB)          // 32768 B per tile (one t x 256 b)
#define P_STAGES 4
#define P_SMEM (P_STAGES * TILEB)   // 131072 B ring -> prefetch distance 3

// ---------------- z-recursion + covs-broadcast config (R8-validated) -------
#define Z_L 32
#define Z_W 48
#define Z_NCHUNK (TT / Z_L)         // 256
#define Z_MAXSTEPS (Z_L + Z_W)      // 80
#define BC_TILE 32
#define BC_NBLK (TT / BC_TILE)      // 256
#define ZB_SMEM (Z_MAXSTEPS * 26 * 4 + NB * 41 * 4)   // 50304 B

// output offsets (tuple flattened: states, covs, ll)
#define OUT_STATES 0
#define OUT_COVS   ((size_t)NB * TT * SD)
#define OUT_LL     (OUT_COVS + (size_t)NB * TT * SD * SD)

// ============================================================================
// Kernel 1: data-independent Riccati recursion -> g_J, g_U
// ============================================================================
__global__ __launch_bounds__(32) void k_ricc(
    const float* __restrict__ Ain,
    const float* __restrict__ Cin,
    const float* __restrict__ Qlog,
    const float* __restrict__ Rlog)
{
    const int chunk = blockIdx.x * 32 + threadIdx.x;

    float a[25];
    #pragma unroll
    for (int i = 0; i < 25; i++) a[i] = Ain[i];
    float q[5];
    #pragma unroll
    for (int k = 0; k < 5; k++) q[k] = expf(Qlog[k]);

    float U[25];
    #pragma unroll
    for (int i = 0; i < 25; i++) U[i] = 0.f;
    float logdetR = 0.f;
    for (int o = 0; o < OD; o++) {
        float rl = Rlog[o];
        logdetR += rl;
        float ri = expf(-rl);
        float cv[5];
        #pragma unroll
        for (int k = 0; k < 5; k++) cv[k] = Cin[o * 5 + k];
        #pragma unroll
        for (int i = 0; i < 5; i++) {
            float f = ri * cv[i];
            #pragma unroll
            for (int j = 0; j < 5; j++) U[i * 5 + j] += f * cv[j];
        }
    }
    if (chunk == 0) {
        #pragma unroll
        for (int i = 0; i < 25; i++) g_U[i] = U[i];
    }

    const int town = chunk * R_LR;
    const int tend = town + R_LR;
    int t0s = town - R_WR; if (t0s < 0) t0s = 0;

    float P[25];
    #pragma unroll
    for (int i = 0; i < 25; i++) P[i] = (i % 6 == 0) ? 1.f : 0.f;

    for (int t = t0s; t < tend; ++t) {
        float Tm[25], Pp[25];
        #pragma unroll
        for (int i = 0; i < 5; i++)
            #pragma unroll
            for (int j = 0; j < 5; j++) {
                float s = 0.f;
                #pragma unroll
                for (int k = 0; k < 5; k++) s += a[i * 5 + k] * P[k * 5 + j];
                Tm[i * 5 + j] = s;
            }
        #pragma unroll
        for (int i = 0; i < 5; i++)
            #pragma unroll
            for (int j = 0; j < 5; j++) {
                float s = 0.f;
                #pragma unroll
                for (int k = 0; k < 5; k++) s += Tm[i * 5 + k] * a[j * 5 + k];
                Pp[i * 5 + j] = s;
            }
        #pragma unroll
        for (int i = 0; i < 5; i++) Pp[i * 5 + i] += q[i];

        float M[25], V[25];
        #pragma unroll
        for (int i = 0; i < 5; i++)
            #pragma unroll
            for (int j = 0; j < 5; j++) {
                float s = (i == j) ? 1.f : 0.f;
                #pragma unroll
                for (int k = 0; k < 5; k++) s += U[i * 5 + k] * Pp[k * 5 + j];
                M[i * 5 + j] = s;
            }
        #pragma unroll
        for (int i = 0; i < 25; i++) V[i] = (i % 6 == 0) ? 1.f : 0.f;
        float det = 1.f;
        #pragma unroll
        for (int k = 0; k < 5; k++) {
            float piv = M[k * 5 + k];
            det *= piv;
            float ip = 1.f / piv;
            #pragma unroll
            for (int j = 0; j < 5; j++) { M[k * 5 + j] *= ip; V[k * 5 + j] *= ip; }
            #pragma unroll
            for (int i2 = 0; i2 < 5; i2++) {
                if (i2 == k) continue;
                float f = M[i2 * 5 + k];
                #pragma unroll
                for (int j = 0; j < 5; j++) {
                    M[i2 * 5 + j] -= f * M[k * 5 + j];
                    V[i2 * 5 + j] -= f * V[k * 5 + j];
                }
            }
        }
        #pragma unroll
        for (int i = 0; i < 5; i++)
            #pragma unroll
            for (int j = 0; j < 5; j++) {
                float s = 0.f;
                #pragma unroll
                for (int k = 0; k < 5; k++) s += Pp[i * 5 + k] * V[k * 5 + j];
                P[i * 5 + j] = s;
            }

        if (t >= town) {
            float ld = logdetR + logf(det);
            #pragma unroll
            for (int e = 0; e < 25; e++) g_J[t * 26 + e] = P[e];
            g_J[t * 26 + 25] = ld;
        }
    }
}

// ---------------- cp.async helpers ----------------
__device__ __forceinline__ void cp16(uint32_t saddr, const void* gaddr) {
    asm volatile("cp.async.cg.shared.global [%0], [%1], 16;"
                 :: "r"(saddr), "l"(gaddr));
}
#define CP_COMMIT() asm volatile("cp.async.commit_group;" ::: "memory")
#define CP_WAIT3()  asm volatile("cp.async.wait_group 3;" ::: "memory")

// XOR swizzle: 16B chunk q of row b goes to chunk q ^ (b & 7)
__device__ __forceinline__ uint32_t sw_off(int b, int q) {
    return (uint32_t)(b * TROWB + ((q ^ (b & 7)) << 4));
}

// ============================================================================
// Kernel 2: observation projection y -> g_proj
// 148 persistent blocks (1/SM), 4-stage cp.async ring (prefetch distance 3
// tiles ~ 8000 cycles) to fully cover queue-inflated DRAM latency.
// ============================================================================
__global__ __launch_bounds__(256) void k_proj(
    const float* __restrict__ y,
    const float* __restrict__ Cin,
    const float* __restrict__ Rlog)
{
    extern __shared__ float sy[];            // [4][NB][32] swizzled stages
    __shared__ float pp[OD * 8];             // {crv0..4, rin, 0, 0} per o
    const int tid = threadIdx.x;

    if (tid < OD) {
        float ri = expf(-Rlog[tid]);
        #pragma unroll
        for (int k = 0; k < 5; k++) pp[tid * 8 + k] = Cin[tid * 5 + k] * ri;
        pp[tid * 8 + 5] = ri;
        pp[tid * 8 + 6] = 0.f;
        pp[tid * 8 + 7] = 0.f;
    }
    __syncthreads();

    const uint32_t sbase = (uint32_t)__cvta_generic_to_shared(sy);
    const char* yb = (const char*)y;
    const int bid = blockIdx.x;

    // prologue: tiles n=0,1,2 into stages 0,1,2
    #pragma unroll
    for (int d = 0; d < 3; ++d) {
        const int tp = bid + d * PP_NBLK;
        if (tp < TT) {
            #pragma unroll
            for (int it = 0; it < 8; ++it) {
                int f = it * 256 + tid;
                int b = f >> 3, q = f & 7;
                cp16(sbase + d * TILEB + sw_off(b, q),
                     yb + ((size_t)b * TT + tp) * 128 + q * 16);
            }
        }
        CP_COMMIT();
    }

    for (int n = 0;; ++n) {
        const int t = bid + n * PP_NBLK;
        if (t >= TT) break;

        // issue tile n+3 into stage (n+3)&3 (freed by barrier at end of n-1)
        const int tp = t + 3 * PP_NBLK;
        if (tp < TT) {
            const int sg = (n + 3) & 3;
            #pragma unroll
            for (int it = 0; it < 8; ++it) {
                int f = it * 256 + tid;
                int b = f >> 3, q = f & 7;
                cp16(sbase + sg * TILEB + sw_off(b, q),
                     yb + ((size_t)b * TT + tp) * 128 + q * 16);
            }
        }
        CP_COMMIT();
        CP_WAIT3();            // tile n's group complete
        __syncthreads();       // visible to all threads

        // compute: thread = batch row b
        const int b = tid;
        const float* base = sy + ((n & 3) * TILEB) / 4;
        float v[OD];
        #pragma unroll
        for (int q = 0; q < 8; q++) {
            const float4 x = *(const float4*)((const char*)base + sw_off(b, q));
            v[q * 4 + 0] = x.x; v[q * 4 + 1] = x.y;
            v[q * 4 + 2] = x.z; v[q * 4 + 3] = x.w;
        }
        float c0 = 0, c1 = 0, c2 = 0, c3 = 0, c4 = 0, syy = 0;
        const float4* p4 = (const float4*)pp;
        #pragma unroll
        for (int o = 0; o < OD; o++) {
            float4 pa = p4[o * 2];
            float4 pb = p4[o * 2 + 1];
            float yv = v[o];
            c0 += pa.x * yv;
            c1 += pa.y * yv;
            c2 += pa.z * yv;
            c3 += pa.w * yv;
            c4 += pb.x * yv;
            syy += (pb.y * yv) * yv;
        }
        float* pd = &g_proj[((size_t)t * 6) * NB + b];
        pd[0 * NB] = c0; pd[1 * NB] = c1; pd[2 * NB] = c2;
        pd[3 * NB] = c3; pd[4 * NB] = c4; pd[5 * NB] = syy;

        __syncthreads();       // stage n reusable only after all reads done
    }
}

// ---------------- one z step ----------------
#define Z_STEP(CCBUF, U_)                                                     \
    {                                                                         \
        float zp[5];                                                          \
        _Pragma("unroll")                                                     \
        for (int i = 0; i < 5; i++)                                           \
            zp[i] = a[i*5+0]*z0 + a[i*5+1]*z1 + a[i*5+2]*z2                   \
                  + a[i*5+3]*z3 + a[i*5+4]*z4;                                \
        float g[5];                                                           \
        _Pragma("unroll")                                                     \
        for (int i = 0; i < 5; i++) {                                         \
            float sa = 0.f;                                                   \
            _Pragma("unroll")                                                 \
            for (int j = 0; j < 5; j++) sa += U_[i*5+j] * zp[j];              \
            g[i] = sa;                                                        \
        }                                                                     \
        float w[5];                                                           \
        _Pragma("unroll")                                                     \
        for (int i = 0; i < 5; i++) w[i] = (CCBUF)[i] - g[i];                 \
        const float* Jr = &sJ[s * 26];                                        \
        float h[5];                                                           \
        _Pragma("unroll")                                                     \
        for (int i = 0; i < 5; i++) {                                         \
            float sa = 0.f;                                                   \
            _Pragma("unroll")                                                 \
            for (int j = 0; j < 5; j++) sa += Jr[i*5+j] * w[j];               \
            h[i] = sa;                                                        \
        }                                                                     \
        z0 = zp[0]+h[0]; z1 = zp[1]+h[1]; z2 = zp[2]+h[2];                    \
        z3 = zp[3]+h[3]; z4 = zp[4]+h[4];                                     \
        if (s >= warm) {                                                      \
            float cz = 0, zg = 0, wh = 0;                                     \
            _Pragma("unroll")                                                 \
            for (int i = 0; i < 5; i++) {                                     \
                cz += (CCBUF)[i]*zp[i]; zg += zp[i]*g[i]; wh += w[i]*h[i];    \
            }                                                                 \
            float quad = (CCBUF)[5] - 2.f*cz + zg - wh;                       \
            ll -= 0.5f * ((float)OD * 1.8378770664093453f                     \
                          + Jr[25] + quad);                                   \
            int sl = (s - warm) & 7;                                          \
            float* sb = &sbuf[b * 41 + sl * 5];                               \
            sb[0]=z0; sb[1]=z1; sb[2]=z2; sb[3]=z3; sb[4]=z4;                 \
        }                                                                     \
    }

// ============================================================================
// Kernel 3: fused  (a) z-recursion + states + ll partials [blocks 0..255]
//                  (b) covariance broadcast J -> covs     [blocks 256..511]
// ============================================================================
__global__ __launch_bounds__(256) void k_zbc(
    const float* __restrict__ Ain, float* __restrict__ out)
{
    extern __shared__ float sm[];
    const int tid = threadIdx.x;

    if (blockIdx.x < Z_NCHUNK) {
        float* sJ   = sm;                         // [Z_MAXSTEPS][26]
        float* sbuf = sm + Z_MAXSTEPS * 26;       // [NB][41]

        const int chunk = blockIdx.x;
        const int town = chunk * Z_L;
        int t0 = town - Z_W; if (t0 < 0) t0 = 0;
        const int nsteps = town + Z_L - t0;       // 32 or 80 (both %8==0)
        const int warm = town - t0;               // 0 or 48

        for (int i = tid; i < nsteps * 26; i += 256) sJ[i] = g_J[t0 * 26 + i];
        __syncthreads();

        float a[25], U[25];
        #pragma unroll
        for (int i = 0; i < 25; i++) { a[i] = Ain[i]; U[i] = g_U[i]; }

        float z0 = 0, z1 = 0, z2 = 0, z3 = 0, z4 = 0;
        float ll = 0.f;
        const int b = tid;
        const float* pbase = &g_proj[(size_t)t0 * 6 * NB + b];

        float bufA[4][6], bufB[4][6];
        #pragma unroll
        for (int u = 0; u < 4; u++)
            #pragma unroll
            for (int k = 0; k < 6; k++)
                bufA[u][k] = pbase[((size_t)u * 6 + k) * NB];

        for (int s8 = 0; s8 < nsteps; s8 += 8) {
            if (s8 + 4 < nsteps) {
                const float* pn = pbase + (size_t)(s8 + 4) * 6 * NB;
                #pragma unroll
                for (int u = 0; u < 4; u++)
                    #pragma unroll
                    for (int k = 0; k < 6; k++)
                        bufB[u][k] = pn[((size_t)u * 6 + k) * NB];
            }
            #pragma unroll
            for (int u = 0; u < 4; u++) {
                const int s = s8 + u;
                Z_STEP(bufA[u], U)
            }
            if (s8 + 8 < nsteps) {
                const float* pn = pbase + (size_t)(s8 + 8) * 6 * NB;
                #pragma unroll
                for (int u = 0; u < 4; u++)
                    #pragma unroll
                    for (int k = 0; k < 6; k++)
                        bufA[u][k] = pn[((size_t)u * 6 + k) * NB];
            }
            #pragma unroll
            for (int u = 0; u < 4; u++) {
                const int s = s8 + 4 + u;
                Z_STEP(bufB[u], U)
            }
            if (s8 >= warm) {
                __syncthreads();
                const int tflush0 = town + (s8 - warm);
                for (int f = tid; f < NB * 40; f += 256) {
                    int bb = f / 40;
                    int u  = f % 40;
                    __stcs(&out[OUT_STATES + ((size_t)bb * TT + tflush0) * 5 + u],
                           sbuf[bb * 41 + u]);
                }
                __syncthreads();
            }
        }
        g_llpart[(size_t)b * Z_NCHUNK + chunk] = ll;
    } else {
        // ---- covariance broadcast: contiguous float4 streaming stores ----
        const int v = blockIdx.x - Z_NCHUNK;       // 0..255
        const int t0 = v * BC_TILE;
        float* sJ = sm;                            // 800 floats
        for (int i = tid; i < BC_TILE * 25; i += 256) {
            int tt = i / 25;
            int e  = i % 25;
            sJ[i] = g_J[(t0 + tt) * 26 + e];
        }
        __syncthreads();
        const float4* sJ4 = (const float4*)sJ;     // 200 float4
        float4* out4 = (float4*)(out + OUT_COVS);
        const unsigned base = (unsigned)v * 200u;
        if (tid < 200) {
            float4 val = sJ4[tid];
            #pragma unroll 4
            for (int bb = 0; bb < NB; ++bb) {
                __stcs(&out4[(size_t)bb * (TT * 25 / 4) + base + tid], val);
            }
        }
    }
}

// ============================================================================
// Kernel 4: ll reduction — block = one batch, 32 lanes, butterfly reduce
// ============================================================================
__global__ __launch_bounds__(32) void k_ll(float* __restrict__ out)
{
    const int b = blockIdx.x;
    const int lane = threadIdx.x;
    const float* p = &g_llpart[(size_t)b * Z_NCHUNK];
    float s = 0.f;
    #pragma unroll
    for (int k = 0; k < Z_NCHUNK / 32; k++) s += p[lane + k * 32];
    #pragma unroll
    for (int d = 16; d >= 1; d >>= 1)
        s += __shfl_xor_sync(0xFFFFFFFFu, s, d);
    if (lane == 0) out[OUT_LL + b] = s;
}

// ============================================================================
extern "C" void kernel_launch(void* const* d_in, const int* in_sizes, int n_in,
                              void* d_out, int out_size)
{
    const float* y  = (const float*)d_in[0];
    const float* A  = (const float*)d_in[1];
    const float* C  = (const float*)d_in[2];
    const float* Ql = (const float*)d_in[3];
    const float* Rl = (const float*)d_in[4];
    float* out = (float*)d_out;

    cudaFuncSetAttribute(k_proj, cudaFuncAttributeMaxDynamicSharedMemorySize, P_SMEM);
    cudaFuncSetAttribute(k_zbc, cudaFuncAttributeMaxDynamicSharedMemorySize, ZB_SMEM);

    k_ricc<<<R_NBLK, 32>>>(A, C, Ql, Rl);
    k_proj<<<PP_NBLK, 256, P_SMEM>>>(y, C, Rl);
    k_zbc<<<Z_NCHUNK + BC_NBLK, 256, ZB_SMEM>>>(A, out);
    k_ll<<<NB, 32>>>(out);
}